// round 14
// baseline (speedup 1.0000x reference)
#include <cuda_runtime.h>
#include <math_constants.h>

// Sparsemax along last dim. (64,1024,512) fp32 -> 65536 rows x 512.
// One warp per row, 16 fp32/lane (4x float4, __ldcs). tau >= max-1 =>
// candidates are x > max-1 (~6/row gaussian). Scan-compact into a 32-entry
// per-warp smem buffer: per-lane candidate count -> ONE warp exclusive
// prefix scan gives each lane its base slot (order irrelevant), replacing
// 16 serial ballots. Newton on f(tau)=sum(relu(x-tau))-1 from tau0=max-1
// (monotone from below, exact on piecewise-linear f); first loop iteration
// doubles as the s0/cnt bootstrap. sm_103: integer redux.sync only ->
// warp max via monotone uint key; Newton (count,sum) in ONE u32 redux:
// (k<<26)|round(t*2^20) (fast path: t in (0,1], sum<=32 -> no carry).
// Epilogue uses packed add.rn.f32x2. 64-thread blocks (best geometry).

#define N_COLS 512
#define WARPS_PER_BLOCK 2          // 64-thread blocks
#define QSCALE 1048576.0f          // 2^20
#define QINV   (1.0f/1048576.0f)

__device__ __forceinline__ unsigned fkey(float x) {
    unsigned b = __float_as_uint(x);
    return b ^ (unsigned)(((int)b >> 31) | 0x80000000);
}
__device__ __forceinline__ float funkey(unsigned k) {
    unsigned m = (unsigned)((~((int)k >> 31)) | 0x80000000);
    return __uint_as_float(k ^ m);
}

__global__ __launch_bounds__(64) void sparsemax_kernel(
    const float* __restrict__ x, float* __restrict__ out, int rows)
{
    __shared__ float cand[WARPS_PER_BLOCK][32];

    const int wib  = threadIdx.x >> 5;
    const int row  = blockIdx.x * WARPS_PER_BLOCK + wib;
    if (row >= rows) return;
    const int lane = threadIdx.x & 31;

    const float4* __restrict__ in = reinterpret_cast<const float4*>(x   + (size_t)row * N_COLS);
    float4*       __restrict__ op = reinterpret_cast<float4*>(      out + (size_t)row * N_COLS);

    float z[16];
    float ml = -CUDART_INF_F;
    #pragma unroll
    for (int i = 0; i < 4; i++) {
        float4 v = __ldcs(&in[i * 32 + lane]);   // streaming: evict-first
        z[i*4+0] = v.x; z[i*4+1] = v.y; z[i*4+2] = v.z; z[i*4+3] = v.w;
        ml = fmaxf(ml, fmaxf(fmaxf(v.x, v.y), fmaxf(v.z, v.w)));
    }
    const float m   = funkey(__reduce_max_sync(0xffffffffu, fkey(ml)));
    const float thr = m - 1.0f;                  // tau >= thr always

    // Per-lane candidate count (no cross-lane ops).
    int nl = 0;
    #pragma unroll
    for (int i = 0; i < 16; i++) nl += (z[i] > thr);

    // One exclusive warp prefix scan -> base slot per lane; total via redux.
    int scan = nl;
    #pragma unroll
    for (int o = 1; o < 32; o <<= 1) {
        int t = __shfl_up_sync(0xffffffffu, scan, o);
        if (lane >= o) scan += t;
    }
    int base = scan - nl;                        // exclusive prefix
    const int cnt = __reduce_add_sync(0xffffffffu, (unsigned)nl);

    // Store candidates at consecutive slots (order irrelevant; clamp to 31 —
    // fast path only used when cnt <= 32 so the clamp is harmless).
    #pragma unroll
    for (int i = 0; i < 16; i++) {
        if (z[i] > thr) {
            cand[wib][base & 31] = z[i];
            base++;
        }
    }
    __syncwarp();                                // STS -> LDS visibility

    // Newton from tau0 = thr; first iteration IS the s0/cnt bootstrap
    // (k = cnt, s = sum(c - thr) >= 1 since the max contributes exactly 1).
    float tau = thr;

    if (cnt <= 32) {
        float c = (lane < cnt) ? cand[wib][lane] : -CUDART_INF_F;
        #pragma unroll 1
        for (int it = 0; it < 32; it++) {
            float t = c - tau;
            bool  p = t > 0.0f;
            unsigned packed = (p ? (1u << 26) : 0u)
                            + __float2uint_rn(fmaxf(t, 0.0f) * QSCALE);
            unsigned r = __reduce_add_sync(0xffffffffu, packed);
            unsigned k = r >> 26;
            if (k == 0) break;
            float s  = (float)(r & 0x03ffffffu) * QINV;
            float tn = tau + __fdividef(s - 1.0f, (float)k);
            if (!(tn > tau + 1e-6f)) {           // quantization floor reached
                tau = fmaxf(tau, tn);
                break;
            }
            tau = tn;
        }
    } else {
        // degenerate rows (many near-max values): rescan registers
        #pragma unroll 1
        for (int it = 0; it < 64; it++) {
            float sl = 0.0f; int kl = 0;
            #pragma unroll
            for (int i = 0; i < 16; i++) {
                float t = z[i] - tau;
                if (t > 0.0f) { sl += t; kl++; }
            }
            unsigned si = __reduce_add_sync(0xffffffffu,
                                            __float2uint_rn(sl * QSCALE));
            int k = __reduce_add_sync(0xffffffffu, (unsigned)kl);
            if (k == 0) break;
            float s  = (float)si * QINV;
            float tn = tau + __fdividef(s - 1.0f, (float)k);
            if (!(tn > tau)) break;
            tau = tn;
        }
    }

    // Epilogue: packed f32x2 subtraction (8 ops for 16 elems), scalar relu.
    unsigned long long ntau2;
    {
        unsigned nt = __float_as_uint(-tau);
        asm("mov.b64 %0, {%1, %1};" : "=l"(ntau2) : "r"(nt));
    }
    #pragma unroll
    for (int i = 0; i < 4; i++) {
        float t0, t1, t2, t3;
        unsigned long long pa, pb, qa, qb;
        asm("mov.b64 %0, {%1, %2};" : "=l"(pa)
            : "f"(z[i*4+0]), "f"(z[i*4+1]));
        asm("mov.b64 %0, {%1, %2};" : "=l"(pb)
            : "f"(z[i*4+2]), "f"(z[i*4+3]));
        asm("add.rn.f32x2 %0, %1, %2;" : "=l"(qa) : "l"(pa), "l"(ntau2));
        asm("add.rn.f32x2 %0, %1, %2;" : "=l"(qb) : "l"(pb), "l"(ntau2));
        asm("mov.b64 {%0, %1}, %2;" : "=f"(t0), "=f"(t1) : "l"(qa));
        asm("mov.b64 {%0, %1}, %2;" : "=f"(t2), "=f"(t3) : "l"(qb));
        float4 v;
        v.x = fmaxf(t0, 0.0f);
        v.y = fmaxf(t1, 0.0f);
        v.z = fmaxf(t2, 0.0f);
        v.w = fmaxf(t3, 0.0f);
        __stcs(&op[i * 32 + lane], v);
    }
}

extern "C" void kernel_launch(void* const* d_in, const int* in_sizes, int n_in,
                              void* d_out, int out_size)
{
    const float* x = (const float*)d_in[0];
    float* out = (float*)d_out;
    const int n = in_sizes[0];
    const int rows = n / N_COLS;

    const int threads = 32 * WARPS_PER_BLOCK;
    const int blocks = (rows + WARPS_PER_BLOCK - 1) / WARPS_PER_BLOCK;
    sparsemax_kernel<<<blocks, threads>>>(x, out, rows);
}

// round 15
// speedup vs baseline: 1.0007x; 1.0007x over previous
#include <cuda_runtime.h>
#include <math_constants.h>

// Sparsemax along last dim. (64,1024,512) fp32 -> 65536 rows x 512.
// One warp per row, 16 fp32/lane (4x float4, __ldcs). tau >= max-1 =>
// candidates are x > max-1 (~6/row gaussian). Scan-compact into a 32-entry
// per-warp smem buffer (one warp prefix scan for slot assignment; order
// irrelevant), accumulating s0 = sum(z-thr) in the same pass for a free
// first Newton step. Newton on f(tau)=sum(relu(x-tau))-1 from tau0=max-1
// (monotone from below, exact on piecewise-linear f).
// sm_103: integer redux.sync only -> warp max via monotone uint key;
// Newton (count,sum) in ONE u32 redux: (k<<26)|round(t*2^20)
// (fast path: t in (0,1], sum <= 32 -> no carry into k field).
// Epilogue uses packed add.rn.f32x2. 64-thread blocks (best geometry).

#define N_COLS 512
#define WARPS_PER_BLOCK 2          // 64-thread blocks
#define QSCALE 1048576.0f          // 2^20
#define QINV   (1.0f/1048576.0f)

__device__ __forceinline__ unsigned fkey(float x) {
    unsigned b = __float_as_uint(x);
    return b ^ (unsigned)(((int)b >> 31) | 0x80000000);
}
__device__ __forceinline__ float funkey(unsigned k) {
    unsigned m = (unsigned)((~((int)k >> 31)) | 0x80000000);
    return __uint_as_float(k ^ m);
}

__global__ __launch_bounds__(64) void sparsemax_kernel(
    const float* __restrict__ x, float* __restrict__ out, int rows)
{
    __shared__ float cand[WARPS_PER_BLOCK][32];

    const int wib  = threadIdx.x >> 5;
    const int row  = blockIdx.x * WARPS_PER_BLOCK + wib;
    if (row >= rows) return;
    const int lane = threadIdx.x & 31;

    const float4* __restrict__ in = reinterpret_cast<const float4*>(x   + (size_t)row * N_COLS);
    float4*       __restrict__ op = reinterpret_cast<float4*>(      out + (size_t)row * N_COLS);

    float z[16];
    float ml = -CUDART_INF_F;
    #pragma unroll
    for (int i = 0; i < 4; i++) {
        float4 v = __ldcs(&in[i * 32 + lane]);   // streaming: evict-first
        z[i*4+0] = v.x; z[i*4+1] = v.y; z[i*4+2] = v.z; z[i*4+3] = v.w;
        ml = fmaxf(ml, fmaxf(fmaxf(v.x, v.y), fmaxf(v.z, v.w)));
    }
    const float m   = funkey(__reduce_max_sync(0xffffffffu, fkey(ml)));
    const float thr = m - 1.0f;                  // tau >= thr always

    // Per-lane candidate count (no cross-lane ops).
    int nl = 0;
    #pragma unroll
    for (int i = 0; i < 16; i++) nl += (z[i] > thr);

    // One exclusive warp prefix scan -> base slot per lane; total via redux.
    int scan = nl;
    #pragma unroll
    for (int o = 1; o < 32; o <<= 1) {
        int t = __shfl_up_sync(0xffffffffu, scan, o);
        if (lane >= o) scan += t;
    }
    int base = scan - nl;                        // exclusive prefix
    const int cnt = __reduce_add_sync(0xffffffffu, (unsigned)nl);

    // Store candidates at consecutive slots (order irrelevant; clamp to 31 —
    // fast path only used when cnt <= 32). Accumulate s0 = sum(z-thr) in
    // the same pass for a free first Newton step.
    float s0l = 0.0f;
    #pragma unroll
    for (int i = 0; i < 16; i++) {
        if (z[i] > thr) {
            s0l += z[i] - thr;
            cand[wib][base & 31] = z[i];
            base++;
        }
    }
    unsigned s0i = __reduce_add_sync(0xffffffffu,
                                     __float2uint_rn(s0l * QSCALE));
    float s0 = (float)s0i * QINV;                // >= 1 (max contributes 1)
    __syncwarp();                                // STS -> LDS visibility

    // First Newton update: tau1 = thr + (s0-1)/cnt (monotone from below)
    float tau = thr + __fdividef(s0 - 1.0f, (float)cnt);

    if (cnt <= 32) {
        float c = (lane < cnt) ? cand[wib][lane] : -CUDART_INF_F;
        #pragma unroll 1
        for (int it = 0; it < 32; it++) {
            float t = c - tau;
            bool  p = t > 0.0f;
            unsigned packed = (p ? (1u << 26) : 0u)
                            + __float2uint_rn(fmaxf(t, 0.0f) * QSCALE);
            unsigned r = __reduce_add_sync(0xffffffffu, packed);
            unsigned k = r >> 26;
            if (k == 0) break;
            float s  = (float)(r & 0x03ffffffu) * QINV;
            float tn = tau + __fdividef(s - 1.0f, (float)k);
            if (!(tn > tau + 1e-6f)) {           // quantization floor reached
                tau = fmaxf(tau, tn);
                break;
            }
            tau = tn;
        }
    } else {
        // degenerate rows (many near-max values): rescan registers
        #pragma unroll 1
        for (int it = 0; it < 64; it++) {
            float sl = 0.0f; int kl = 0;
            #pragma unroll
            for (int i = 0; i < 16; i++) {
                float t = z[i] - tau;
                if (t > 0.0f) { sl += t; kl++; }
            }
            unsigned si = __reduce_add_sync(0xffffffffu,
                                            __float2uint_rn(sl * QSCALE));
            int k = __reduce_add_sync(0xffffffffu, (unsigned)kl);
            if (k == 0) break;
            float s  = (float)si * QINV;
            float tn = tau + __fdividef(s - 1.0f, (float)k);
            if (!(tn > tau)) break;
            tau = tn;
        }
    }

    // Epilogue: packed f32x2 subtraction (8 ops for 16 elems), scalar relu.
    unsigned long long ntau2;
    {
        unsigned nt = __float_as_uint(-tau);
        asm("mov.b64 %0, {%1, %1};" : "=l"(ntau2) : "r"(nt));
    }
    #pragma unroll
    for (int i = 0; i < 4; i++) {
        float t0, t1, t2, t3;
        unsigned long long pa, pb, qa, qb;
        asm("mov.b64 %0, {%1, %2};" : "=l"(pa)
            : "f"(z[i*4+0]), "f"(z[i*4+1]));
        asm("mov.b64 %0, {%1, %2};" : "=l"(pb)
            : "f"(z[i*4+2]), "f"(z[i*4+3]));
        asm("add.rn.f32x2 %0, %1, %2;" : "=l"(qa) : "l"(pa), "l"(ntau2));
        asm("add.rn.f32x2 %0, %1, %2;" : "=l"(qb) : "l"(pb), "l"(ntau2));
        asm("mov.b64 {%0, %1}, %2;" : "=f"(t0), "=f"(t1) : "l"(qa));
        asm("mov.b64 {%0, %1}, %2;" : "=f"(t2), "=f"(t3) : "l"(qb));
        float4 v;
        v.x = fmaxf(t0, 0.0f);
        v.y = fmaxf(t1, 0.0f);
        v.z = fmaxf(t2, 0.0f);
        v.w = fmaxf(t3, 0.0f);
        __stcs(&op[i * 32 + lane], v);
    }
}

extern "C" void kernel_launch(void* const* d_in, const int* in_sizes, int n_in,
                              void* d_out, int out_size)
{
    const float* x = (const float*)d_in[0];
    float* out = (float*)d_out;
    const int n = in_sizes[0];
    const int rows = n / N_COLS;

    const int threads = 32 * WARPS_PER_BLOCK;
    const int blocks = (rows + WARPS_PER_BLOCK - 1) / WARPS_PER_BLOCK;
    sparsemax_kernel<<<blocks, threads>>>(x, out, rows);
}